// round 3
// baseline (speedup 1.0000x reference)
#include <cuda_runtime.h>

// Emformer layer, sm_103a. Round 3: projections on tensor cores (tf32 mma.sync),
// flash attention still fp32 SIMT.
// T=1024 B=16 D=512 H=8 R=32 S=16 M=16  TQ=KL=1072, d_head=64, B*H=128.

#define TT    1024
#define BB    16
#define DD    512
#define HH    8
#define RR    32
#define SSUM  16
#define MMEM  16
#define TQL   1072
#define KLL   1072
#define DH    64
#define NH    128          // B*H
#define NEG_INF (-100000000.0f)
#define QSCALE  (0.125f)   // 64^-0.5

// Scratch (device globals: allocation-free rule)
__device__ float g_q   [(size_t)NH * TQL * DH];
__device__ float g_k   [(size_t)NH * KLL * DH];
__device__ float g_v   [(size_t)NH * KLL * DH];
__device__ float g_attn[(size_t)NH * TQL * DH];

// lengths may be int32 (JAX default, x64 disabled) or int64. Values are in
// [T/2, T] = [512,1024], all nonzero -> int64 layout has zero high words.
__device__ __forceinline__ int read_len(const void* lptr, int b) {
    const int* p32 = (const int*)lptr;
    const bool is64 = (p32[1] == 0) & (p32[3] == 0) & (p32[5] == 0);
    return is64 ? (int)(((const long long*)lptr)[b]) : p32[b];
}

// ---------------------------------------------------------------------------
// tf32 mma helpers
// ---------------------------------------------------------------------------
__device__ __forceinline__ unsigned f2tf32(float x) {
    unsigned r;
    asm("cvt.rna.tf32.f32 %0, %1;" : "=r"(r) : "f"(x));
    return r;
}
__device__ __forceinline__ void cvt4(unsigned* dst, float4 v) {
    dst[0] = f2tf32(v.x); dst[1] = f2tf32(v.y);
    dst[2] = f2tf32(v.z); dst[3] = f2tf32(v.w);
}
__device__ __forceinline__ void mma_tf32(float* c, const unsigned* a,
                                         unsigned b0, unsigned b1) {
    asm("mma.sync.aligned.m16n8k8.row.col.f32.tf32.tf32.f32 "
        "{%0,%1,%2,%3},{%4,%5,%6,%7},{%8,%9},{%0,%1,%2,%3};"
        : "+f"(c[0]), "+f"(c[1]), "+f"(c[2]), "+f"(c[3])
        : "r"(a[0]), "r"(a[1]), "r"(a[2]), "r"(a[3]), "r"(b0), "r"(b1));
}

// Shared tile geometry: block tile M=128 (rows t), N=64 (cols), K-chunk 32.
// 256 threads = 8 warps as 4(m) x 2(n); each warp 32x32 = 2 m-tiles x 4 n-tiles.
#define KPAD 36
#define STORE4(ptr, v4) do { unsigned _t[4]; cvt4(_t, v4); \
    *(uint4*)(ptr) = make_uint4(_t[0], _t[1], _t[2], _t[3]); } while (0)

// MMA core over one K-chunk already resident in As/Bs.
__device__ __forceinline__ void mma_chunk(const unsigned* As, const unsigned* Bs,
                                          int warpM, int warpN, int g, int tg,
                                          float acc[2][4][4]) {
#pragma unroll
    for (int k8 = 0; k8 < 32; k8 += 8) {
        unsigned a[2][4];
#pragma unroll
        for (int mt = 0; mt < 2; mt++) {
            const int rb = warpM + mt * 16;
            a[mt][0] = As[(rb + g)     * KPAD + k8 + tg];
            a[mt][1] = As[(rb + 8 + g) * KPAD + k8 + tg];
            a[mt][2] = As[(rb + g)     * KPAD + k8 + tg + 4];
            a[mt][3] = As[(rb + 8 + g) * KPAD + k8 + tg + 4];
        }
        unsigned bf[4][2];
#pragma unroll
        for (int nt = 0; nt < 4; nt++) {
            const int cb = warpN + nt * 8;
            bf[nt][0] = Bs[(cb + g) * KPAD + k8 + tg];
            bf[nt][1] = Bs[(cb + g) * KPAD + k8 + tg + 4];
        }
#pragma unroll
        for (int mt = 0; mt < 2; mt++)
#pragma unroll
            for (int nt = 0; nt < 4; nt++)
                mma_tf32(acc[mt][nt], a[mt], bf[nt][0], bf[nt][1]);
    }
}

// ---------------------------------------------------------------------------
// Q projection (tensor): g_q[b*H+h][t][dh] = (gather_q(t,b,:).Wq[h*64+dh,:]+bq)*QSCALE
// ---------------------------------------------------------------------------
__global__ void __launch_bounds__(256) proj_q_kernel(
    const float* __restrict__ utt, const float* __restrict__ rc,
    const float* __restrict__ summ, const float* __restrict__ W,
    const float* __restrict__ bias)
{
    __shared__ unsigned As[128 * KPAD];
    __shared__ unsigned Bs[64 * KPAD];
    const int t0 = blockIdx.x * 128;
    const int h  = blockIdx.y;
    const int b  = blockIdx.z;
    const int tid = threadIdx.x;
    const int lane = tid & 31, wid = tid >> 5;
    const int g = lane >> 2, tg = lane & 3;
    const int warpM = (wid & 3) * 32, warpN = (wid >> 2) * 32;
    const int lr = tid >> 2, lc = tid & 3;

    auto gather = [&](int t) -> const float* {
        if (t < RR)           return rc   + ((size_t)t * BB + b) * DD;
        if (t < RR + TT)      return utt  + ((size_t)(t - RR) * BB + b) * DD;
        if (t < TQL)          return summ + ((size_t)(t - RR - TT) * BB + b) * DD;
        return nullptr;
    };
    const float* arow0 = gather(t0 + lr);
    const float* arow1 = gather(t0 + 64 + lr);
    const float* brow  = W + (size_t)(h * 64 + lr) * DD;

    float acc[2][4][4];
#pragma unroll
    for (int mt = 0; mt < 2; mt++)
#pragma unroll
        for (int nt = 0; nt < 4; nt++)
#pragma unroll
            for (int i = 0; i < 4; i++) acc[mt][nt][i] = 0.f;

    const float4 Z = make_float4(0, 0, 0, 0);
    for (int k0 = 0; k0 < DD; k0 += 32) {
        float4 a00 = arow0 ? *(const float4*)(arow0 + k0 + lc * 4) : Z;
        float4 a01 = arow0 ? *(const float4*)(arow0 + k0 + 16 + lc * 4) : Z;
        float4 a10 = arow1 ? *(const float4*)(arow1 + k0 + lc * 4) : Z;
        float4 a11 = arow1 ? *(const float4*)(arow1 + k0 + 16 + lc * 4) : Z;
        float4 b0v = *(const float4*)(brow + k0 + lc * 4);
        float4 b1v = *(const float4*)(brow + k0 + 16 + lc * 4);
        __syncthreads();
        STORE4(As + lr * KPAD + lc * 4, a00);
        STORE4(As + lr * KPAD + lc * 4 + 16, a01);
        STORE4(As + (lr + 64) * KPAD + lc * 4, a10);
        STORE4(As + (lr + 64) * KPAD + lc * 4 + 16, a11);
        STORE4(Bs + lr * KPAD + lc * 4, b0v);
        STORE4(Bs + lr * KPAD + lc * 4 + 16, b1v);
        __syncthreads();
        mma_chunk(As, Bs, warpM, warpN, g, tg, acc);
    }

    const size_t nb = ((size_t)(b * HH + h)) * TQL;
#pragma unroll
    for (int mt = 0; mt < 2; mt++) {
#pragma unroll
        for (int nt = 0; nt < 4; nt++) {
            const int c0 = warpN + nt * 8 + 2 * tg;
            const float bx = bias[h * 64 + c0], by = bias[h * 64 + c0 + 1];
#pragma unroll
            for (int half = 0; half < 2; half++) {
                const int t = t0 + warpM + mt * 16 + half * 8 + g;
                if (t < TQL) {
                    float2 v;
                    v.x = (acc[mt][nt][half * 2 + 0] + bx) * QSCALE;
                    v.y = (acc[mt][nt][half * 2 + 1] + by) * QSCALE;
                    *(float2*)(g_q + (nb + t) * DH + c0) = v;
                }
            }
        }
    }
}

// ---------------------------------------------------------------------------
// KV projection (tensor): cb 0..7 -> K head cb; 8..15 -> V head cb-8.
// ---------------------------------------------------------------------------
__global__ void __launch_bounds__(256) proj_kv_kernel(
    const float* __restrict__ mems, const float* __restrict__ rc,
    const float* __restrict__ utt, const float* __restrict__ W,
    const float* __restrict__ bias)
{
    __shared__ unsigned As[128 * KPAD];
    __shared__ unsigned Bs[64 * KPAD];
    const int t0 = blockIdx.x * 128;
    const int cb = blockIdx.y;          // 0..15
    const int b  = blockIdx.z;
    const int tid = threadIdx.x;
    const int lane = tid & 31, wid = tid >> 5;
    const int g = lane >> 2, tg = lane & 3;
    const int warpM = (wid & 3) * 32, warpN = (wid >> 2) * 32;
    const int lr = tid >> 2, lc = tid & 3;

    auto gather = [&](int t) -> const float* {
        if (t < MMEM)            return mems + ((size_t)t * BB + b) * DD;
        if (t < MMEM + RR)       return rc   + ((size_t)(t - MMEM) * BB + b) * DD;
        if (t < KLL)             return utt  + ((size_t)(t - MMEM - RR) * BB + b) * DD;
        return nullptr;
    };
    const float* arow0 = gather(t0 + lr);
    const float* arow1 = gather(t0 + 64 + lr);
    const float* brow  = W + (size_t)(cb * 64 + lr) * DD;

    float acc[2][4][4];
#pragma unroll
    for (int mt = 0; mt < 2; mt++)
#pragma unroll
        for (int nt = 0; nt < 4; nt++)
#pragma unroll
            for (int i = 0; i < 4; i++) acc[mt][nt][i] = 0.f;

    const float4 Z = make_float4(0, 0, 0, 0);
    for (int k0 = 0; k0 < DD; k0 += 32) {
        float4 a00 = arow0 ? *(const float4*)(arow0 + k0 + lc * 4) : Z;
        float4 a01 = arow0 ? *(const float4*)(arow0 + k0 + 16 + lc * 4) : Z;
        float4 a10 = arow1 ? *(const float4*)(arow1 + k0 + lc * 4) : Z;
        float4 a11 = arow1 ? *(const float4*)(arow1 + k0 + 16 + lc * 4) : Z;
        float4 b0v = *(const float4*)(brow + k0 + lc * 4);
        float4 b1v = *(const float4*)(brow + k0 + 16 + lc * 4);
        __syncthreads();
        STORE4(As + lr * KPAD + lc * 4, a00);
        STORE4(As + lr * KPAD + lc * 4 + 16, a01);
        STORE4(As + (lr + 64) * KPAD + lc * 4, a10);
        STORE4(As + (lr + 64) * KPAD + lc * 4 + 16, a11);
        STORE4(Bs + lr * KPAD + lc * 4, b0v);
        STORE4(Bs + lr * KPAD + lc * 4 + 16, b1v);
        __syncthreads();
        mma_chunk(As, Bs, warpM, warpN, g, tg, acc);
    }

    float* dst = (cb < HH) ? g_k : g_v;
    const int h = cb & 7;
    const size_t nb = ((size_t)(b * HH + h)) * KLL;
#pragma unroll
    for (int mt = 0; mt < 2; mt++) {
#pragma unroll
        for (int nt = 0; nt < 4; nt++) {
            const int c0 = warpN + nt * 8 + 2 * tg;
            const float bx = bias[cb * 64 + c0], by = bias[cb * 64 + c0 + 1];
#pragma unroll
            for (int half = 0; half < 2; half++) {
                const int t = t0 + warpM + mt * 16 + half * 8 + g;
                if (t < KLL) {
                    float2 v;
                    v.x = acc[mt][nt][half * 2 + 0] + bx;
                    v.y = acc[mt][nt][half * 2 + 1] + by;
                    *(float2*)(dst + (nb + t) * DH + c0) = v;
                }
            }
        }
    }
}

// ---------------------------------------------------------------------------
// Flash attention (fp32 SIMT, unchanged): block = (q-tile 64, n).
// ---------------------------------------------------------------------------
#define FP 68
__global__ void __launch_bounds__(256) flash_kernel(const void* __restrict__ lengths)
{
    extern __shared__ float sm[];
    float* sQ = sm;                 // [64 d][FP] transposed
    float* sK = sm + 64 * FP;
    float* sV = sm + 2 * 64 * FP;
    float* sP = sm + 3 * 64 * FP;

    const int qt = gridDim.x - 1 - blockIdx.x;
    const int n  = blockIdx.y;
    const int b  = n >> 3;
    const int q0 = qt * 64;
    const int tid = threadIdx.x;
    const int tx = tid & 15, ty = tid >> 4;
    const int lr = tid >> 2, lc = tid & 3;

    int ml = read_len(lengths, 0);
#pragma unroll
    for (int i = 1; i < BB; i++) { int v = read_len(lengths, i); if (v > ml) ml = v; }
    const int klen = read_len(lengths, b) + MMEM + (TQL - ml - SSUM);

    {
        const int q = q0 + lr;
        const float* qrow = (q < TQL) ? (g_q + ((size_t)n * TQL + q) * DH) : nullptr;
#pragma unroll
        for (int c = 0; c < 4; c++) {
            const int c4 = (lc + 4 * c) * 4;
            float4 v = qrow ? *(const float4*)(qrow + c4) : make_float4(0,0,0,0);
            sQ[(c4+0)*FP + lr] = v.x; sQ[(c4+1)*FP + lr] = v.y;
            sQ[(c4+2)*FP + lr] = v.z; sQ[(c4+3)*FP + lr] = v.w;
        }
    }

    float m_i[4], l_i[4], o[4][4];
#pragma unroll
    for (int i = 0; i < 4; i++) {
        m_i[i] = NEG_INF; l_i[i] = 0.f;
#pragma unroll
        for (int j = 0; j < 4; j++) o[i][j] = 0.f;
    }

    const int nkt = min(17, qt + 2);
    for (int kt = 0; kt < nkt; kt++) {
        const int k0 = kt * 64;
        __syncthreads();
        {
            const int kk = k0 + lr;
            const bool ok = kk < KLL;
            const float* krow = g_k + ((size_t)n * KLL + (ok ? kk : 0)) * DH;
            const float* vrow = g_v + ((size_t)n * KLL + (ok ? kk : 0)) * DH;
#pragma unroll
            for (int c = 0; c < 4; c++) {
                const int c4 = (lc + 4 * c) * 4;
                float4 kv = ok ? *(const float4*)(krow + c4) : make_float4(0,0,0,0);
                float4 vv = ok ? *(const float4*)(vrow + c4) : make_float4(0,0,0,0);
                sK[(c4+0)*FP + lr] = kv.x; sK[(c4+1)*FP + lr] = kv.y;
                sK[(c4+2)*FP + lr] = kv.z; sK[(c4+3)*FP + lr] = kv.w;
                *(float4*)(sV + lr * FP + c4) = vv;
            }
        }
        __syncthreads();

        float s[4][4];
#pragma unroll
        for (int i = 0; i < 4; i++)
#pragma unroll
            for (int j = 0; j < 4; j++) s[i][j] = 0.f;
#pragma unroll 8
        for (int d = 0; d < DH; d++) {
            float4 av = *(const float4*)(sQ + d * FP + ty * 4);
            float4 bv = *(const float4*)(sK + d * FP + tx * 4);
            float aa[4] = {av.x, av.y, av.z, av.w};
            float bb[4] = {bv.x, bv.y, bv.z, bv.w};
#pragma unroll
            for (int i = 0; i < 4; i++)
#pragma unroll
                for (int j = 0; j < 4; j++) s[i][j] += aa[i] * bb[j];
        }

#pragma unroll
        for (int i = 0; i < 4; i++) {
            const int q = q0 + ty * 4 + i;
            float rmax = NEG_INF;
#pragma unroll
            for (int j = 0; j < 4; j++) {
                const int k = k0 + tx * 4 + j;
                const bool valid = (k <= q + MMEM) && (k < klen) && (k < KLL);
                s[i][j] = valid ? s[i][j] : NEG_INF;
                rmax = fmaxf(rmax, s[i][j]);
            }
#pragma unroll
            for (int off = 1; off < 16; off <<= 1)
                rmax = fmaxf(rmax, __shfl_xor_sync(0xffffffffu, rmax, off));
            const float mnew = fmaxf(m_i[i], rmax);
            const float corr = __expf(m_i[i] - mnew);
            m_i[i] = mnew;
            float rsum = 0.f;
#pragma unroll
            for (int j = 0; j < 4; j++) {
                const float p = __expf(s[i][j] - mnew);
                s[i][j] = p;
                rsum += p;
            }
#pragma unroll
            for (int off = 1; off < 16; off <<= 1)
                rsum += __shfl_xor_sync(0xffffffffu, rsum, off);
            l_i[i] = l_i[i] * corr + rsum;
#pragma unroll
            for (int j = 0; j < 4; j++) o[i][j] *= corr;
        }

#pragma unroll
        for (int j = 0; j < 4; j++)
#pragma unroll
            for (int i = 0; i < 4; i++)
                sP[(tx * 4 + j) * FP + ty * 4 + i] = s[i][j];
        __syncthreads();
#pragma unroll 8
        for (int k = 0; k < 64; k++) {
            float4 av = *(const float4*)(sP + k * FP + ty * 4);
            float4 bv = *(const float4*)(sV + k * FP + tx * 4);
            float aa[4] = {av.x, av.y, av.z, av.w};
            float bb[4] = {bv.x, bv.y, bv.z, bv.w};
#pragma unroll
            for (int i = 0; i < 4; i++)
#pragma unroll
                for (int j = 0; j < 4; j++) o[i][j] += aa[i] * bb[j];
        }
    }

#pragma unroll
    for (int i = 0; i < 4; i++) {
        const int q = q0 + ty * 4 + i;
        if (q < TQL) {
            const float inv = 1.f / l_i[i];
            float4 v;
            v.x = o[i][0] * inv; v.y = o[i][1] * inv;
            v.z = o[i][2] * inv; v.w = o[i][3] * inv;
            *(float4*)(g_attn + ((size_t)n * TQL + q) * DH + tx * 4) = v;
        }
    }
}

// ---------------------------------------------------------------------------
// Output projection (tensor) + split/clip writeback.
// ---------------------------------------------------------------------------
__global__ void __launch_bounds__(256) out_proj_kernel(
    const float* __restrict__ W, const float* __restrict__ bias,
    float* __restrict__ out)
{
    __shared__ unsigned As[128 * KPAD];
    __shared__ unsigned Bs[64 * KPAD];
    const int t0 = blockIdx.x * 128;
    const int cby = blockIdx.y;
    const int b  = blockIdx.z;
    const int tid = threadIdx.x;
    const int lane = tid & 31, wid = tid >> 5;
    const int g = lane >> 2, tg = lane & 3;
    const int warpM = (wid & 3) * 32, warpN = (wid >> 2) * 32;
    const int lr = tid >> 2, lc = tid & 3;

    const int tA0 = t0 + lr, tA1 = t0 + 64 + lr;
    const float* brow = W + (size_t)(cby * 64 + lr) * DD;

    float acc[2][4][4];
#pragma unroll
    for (int mt = 0; mt < 2; mt++)
#pragma unroll
        for (int nt = 0; nt < 4; nt++)
#pragma unroll
            for (int i = 0; i < 4; i++) acc[mt][nt][i] = 0.f;

    const float4 Z = make_float4(0, 0, 0, 0);
    for (int k0 = 0; k0 < DD; k0 += 32) {
        const int hh = k0 >> 6, ko = k0 & 63;
        const float* arow0 = (tA0 < TQL) ?
            g_attn + ((size_t)(b * HH + hh) * TQL + tA0) * DH + ko : nullptr;
        const float* arow1 = (tA1 < TQL) ?
            g_attn + ((size_t)(b * HH + hh) * TQL + tA1) * DH + ko : nullptr;
        float4 a00 = arow0 ? *(const float4*)(arow0 + lc * 4) : Z;
        float4 a01 = arow0 ? *(const float4*)(arow0 + 16 + lc * 4) : Z;
        float4 a10 = arow1 ? *(const float4*)(arow1 + lc * 4) : Z;
        float4 a11 = arow1 ? *(const float4*)(arow1 + 16 + lc * 4) : Z;
        float4 b0v = *(const float4*)(brow + k0 + lc * 4);
        float4 b1v = *(const float4*)(brow + k0 + 16 + lc * 4);
        __syncthreads();
        STORE4(As + lr * KPAD + lc * 4, a00);
        STORE4(As + lr * KPAD + lc * 4 + 16, a01);
        STORE4(As + (lr + 64) * KPAD + lc * 4, a10);
        STORE4(As + (lr + 64) * KPAD + lc * 4 + 16, a11);
        STORE4(Bs + lr * KPAD + lc * 4, b0v);
        STORE4(Bs + lr * KPAD + lc * 4 + 16, b1v);
        __syncthreads();
        mma_chunk(As, Bs, warpM, warpN, g, tg, acc);
    }

    const size_t mems_base = (size_t)(TQL - SSUM) * BB * DD;   // 1056*16*512
#pragma unroll
    for (int mt = 0; mt < 2; mt++) {
#pragma unroll
        for (int nt = 0; nt < 4; nt++) {
            const int c0 = cby * 64 + warpN + nt * 8 + 2 * tg;
            const float bx = bias[c0], by = bias[c0 + 1];
#pragma unroll
            for (int half = 0; half < 2; half++) {
                const int tt = t0 + warpM + mt * 16 + half * 8 + g;
                if (tt >= TQL - 1) continue;         // drop t=1071 + padding
                float2 v;
                v.x = acc[mt][nt][half * 2 + 0] + bx;
                v.y = acc[mt][nt][half * 2 + 1] + by;
                if (tt < TQL - SSUM) {
                    *(float2*)(out + ((size_t)tt * BB + b) * DD + c0) = v;
                } else {
                    v.x = fminf(fmaxf(v.x, -10.f), 10.f);
                    v.y = fminf(fmaxf(v.y, -10.f), 10.f);
                    *(float2*)(out + mems_base +
                               ((size_t)(tt - (TQL - SSUM)) * BB + b) * DD + c0) = v;
                }
            }
        }
    }
}

// ---------------------------------------------------------------------------
extern "C" void kernel_launch(void* const* d_in, const int* in_sizes, int n_in,
                              void* d_out, int out_size)
{
    const float* utt  = (const float*)d_in[0];
    const void*  len  = (const void*)d_in[1];   // int32 or int64, sniffed in-kernel
    const float* rc   = (const float*)d_in[2];
    const float* summ = (const float*)d_in[3];
    const float* mems = (const float*)d_in[4];
    // d_in[5] = attention_mask (deterministic; computed analytically in-kernel)
    const float* Wq   = (const float*)d_in[6];
    const float* bq   = (const float*)d_in[7];
    const float* Wkv  = (const float*)d_in[8];
    const float* bkv  = (const float*)d_in[9];
    const float* Wo   = (const float*)d_in[10];
    const float* bo   = (const float*)d_in[11];
    float* out = (float*)d_out;

    const int flash_smem = 4 * 64 * FP * (int)sizeof(float);   // 69632 B
    cudaFuncSetAttribute(flash_kernel,
                         cudaFuncAttributeMaxDynamicSharedMemorySize, flash_smem);

    proj_q_kernel  <<<dim3(9, 8, BB), 256>>>(utt, rc, summ, Wq, bq);
    proj_kv_kernel <<<dim3(9, 16, BB), 256>>>(mems, rc, utt, Wkv, bkv);
    flash_kernel   <<<dim3(17, NH), 256, flash_smem>>>(len);
    out_proj_kernel<<<dim3(9, 8, BB), 256>>>(Wo, bo, out);
}

// round 4
// speedup vs baseline: 1.9862x; 1.9862x over previous
#include <cuda_runtime.h>
#include <cstdint>

// Emformer layer, sm_103a. Round 4: all GEMMs on tf32 mma.sync with
// fragment-order smem (LDS.128 reads, conflict-free). Flash attention on
// tensor cores; softmax fp32.
// T=1024 B=16 D=512 H=8 R=32 S=16 M=16  TQ=KL=1072, d_head=64, B*H=128.

#define TT    1024
#define BB    16
#define DDIM  512
#define HH    8
#define RR    32
#define SSUM  16
#define MMEM  16
#define TQL   1072
#define KLL   1072
#define DH    64
#define NH    128
#define NEG_INF (-100000000.0f)
#define QSCALE  (0.125f)

__device__ float g_q   [(size_t)NH * TQL * DH];
__device__ float g_k   [(size_t)NH * KLL * DH];
__device__ float g_v   [(size_t)NH * KLL * DH];
__device__ float g_attn[(size_t)NH * TQL * DH];

// lengths may be int32 (JAX default) or int64; values in [512,1024] nonzero.
__device__ __forceinline__ int read_len(const void* lptr, int b) {
    const int* p32 = (const int*)lptr;
    const bool is64 = (p32[1] == 0) & (p32[3] == 0) & (p32[5] == 0);
    return is64 ? (int)(((const long long*)lptr)[b]) : p32[b];
}

__device__ __forceinline__ unsigned f2t(float x) {
    unsigned r;
    asm("cvt.rna.tf32.f32 %0, %1;" : "=r"(r) : "f"(x));
    return r;
}
__device__ __forceinline__ void mma_t(float c[4], uint4 a, unsigned b0, unsigned b1) {
    asm("mma.sync.aligned.m16n8k8.row.col.f32.tf32.tf32.f32 "
        "{%0,%1,%2,%3},{%4,%5,%6,%7},{%8,%9},{%0,%1,%2,%3};"
        : "+f"(c[0]), "+f"(c[1]), "+f"(c[2]), "+f"(c[3])
        : "r"(a.x), "r"(a.y), "r"(a.z), "r"(a.w), "r"(b0), "r"(b1));
}

// Fragment-order smem layout:
//  A (row-major MxK): unit (m16, k8) = 128 words: [lane = (r&7)*4 + (c&3)][slot]
//    slot = 2*((c&7)>>2) + ((r&15)>>3); reg order (a0,a1,a2,a3).
//  B (n-major NxK):   unit (n16, k8): [lane = (n&7)*4 + (c&3)][slot]
//    slot = 2*((n&15)>>3) + ((c&7)>>2); uint4 = (b0_even, b1_even, b0_odd, b1_odd).

// ---------------------------------------------------------------------------
// Projection core: block tile M=128 x N=64, K-chunk 32, 8 warps (4m x 2n).
// ---------------------------------------------------------------------------
struct ProjSmem { unsigned Af[128 * 32]; unsigned Bf[64 * 32]; };

__device__ __forceinline__ void proj_chunk(
    ProjSmem& s, const float* ar0, const float* ar1, int aoff,
    const float* wr0, const float* wr1, int woff,
    int lid, int wid, float acc[2][4][4])
{
    __syncthreads();
    // A store: m16 = wid, k8 = u
#pragma unroll
    for (int u = 0; u < 4; u++) {
        const int c = aoff + u * 8 + (lid & 3);
        uint4 w;
        w.x = f2t(ar0 ? ar0[c] : 0.f);
        w.y = f2t(ar1 ? ar1[c] : 0.f);
        w.z = f2t(ar0 ? ar0[c + 4] : 0.f);
        w.w = f2t(ar1 ? ar1[c + 4] : 0.f);
        ((uint4*)s.Af)[(wid * 4 + u) * 32 + lid] = w;
    }
    // B store: n16 = wid>>1, k8 = (wid&1)*2 + u
#pragma unroll
    for (int u = 0; u < 2; u++) {
        const int k8 = (wid & 1) * 2 + u;
        const int c = woff + k8 * 8 + (lid & 3);
        uint4 w;
        w.x = f2t(wr0[c]); w.y = f2t(wr0[c + 4]);
        w.z = f2t(wr1[c]); w.w = f2t(wr1[c + 4]);
        ((uint4*)s.Bf)[((wid >> 1) * 4 + k8) * 32 + lid] = w;
    }
    __syncthreads();
    const uint4* A4 = (const uint4*)s.Af;
    const uint4* B4 = (const uint4*)s.Bf;
    const int m16 = (wid & 3) * 2, n16 = (wid >> 2) * 2;
#pragma unroll
    for (int k8 = 0; k8 < 4; k8++) {
        uint4 a0 = A4[(m16 * 4 + k8) * 32 + lid];
        uint4 a1 = A4[((m16 + 1) * 4 + k8) * 32 + lid];
        uint4 b0 = B4[(n16 * 4 + k8) * 32 + lid];
        uint4 b1 = B4[((n16 + 1) * 4 + k8) * 32 + lid];
        mma_t(acc[0][0], a0, b0.x, b0.y); mma_t(acc[0][1], a0, b0.z, b0.w);
        mma_t(acc[0][2], a0, b1.x, b1.y); mma_t(acc[0][3], a0, b1.z, b1.w);
        mma_t(acc[1][0], a1, b0.x, b0.y); mma_t(acc[1][1], a1, b0.z, b0.w);
        mma_t(acc[1][2], a1, b1.x, b1.y); mma_t(acc[1][3], a1, b1.z, b1.w);
    }
}

#define PROJ_PROLOG \
    const int tid = threadIdx.x; \
    const int lid = tid & 31, wid = tid >> 5; \
    const int g = lid >> 2, tg = lid & 3; \
    const int warpM = (wid & 3) * 32, warpN = (wid >> 2) * 32; \
    float acc[2][4][4]; \
    _Pragma("unroll") for (int mt = 0; mt < 2; mt++) \
    _Pragma("unroll") for (int nt = 0; nt < 4; nt++) \
    _Pragma("unroll") for (int i = 0; i < 4; i++) acc[mt][nt][i] = 0.f;

// ---------------------------------------------------------------------------
__global__ void __launch_bounds__(256) proj_q_kernel(
    const float* __restrict__ utt, const float* __restrict__ rc,
    const float* __restrict__ summ, const float* __restrict__ W,
    const float* __restrict__ bias)
{
    __shared__ ProjSmem s;
    const int t0 = blockIdx.x * 128;
    const int h = blockIdx.y, b = blockIdx.z;
    PROJ_PROLOG;

    auto gather = [&](int t) -> const float* {
        if (t < RR)      return rc   + ((size_t)t * BB + b) * DDIM;
        if (t < RR + TT) return utt  + ((size_t)(t - RR) * BB + b) * DDIM;
        if (t < TQL)     return summ + ((size_t)(t - RR - TT) * BB + b) * DDIM;
        return nullptr;
    };
    const int ta = t0 + wid * 16 + g;
    const float* ar0 = gather(ta);
    const float* ar1 = gather(ta + 8);
    const float* wr0 = W + (size_t)(h * 64 + (wid >> 1) * 16 + g) * DDIM;
    const float* wr1 = wr0 + 8 * DDIM;

    for (int k0 = 0; k0 < DDIM; k0 += 32)
        proj_chunk(s, ar0, ar1, k0, wr0, wr1, k0, lid, wid, acc);

    const size_t nb = ((size_t)(b * HH + h)) * TQL;
#pragma unroll
    for (int mt = 0; mt < 2; mt++)
#pragma unroll
    for (int nt = 0; nt < 4; nt++) {
        const int c0 = warpN + nt * 8 + 2 * tg;
        const float bx = bias[h * 64 + c0], by = bias[h * 64 + c0 + 1];
#pragma unroll
        for (int rh = 0; rh < 2; rh++) {
            const int t = t0 + warpM + mt * 16 + rh * 8 + g;
            if (t < TQL) {
                float2 v;
                v.x = (acc[mt][nt][rh * 2 + 0] + bx) * QSCALE;
                v.y = (acc[mt][nt][rh * 2 + 1] + by) * QSCALE;
                *(float2*)(g_q + (nb + t) * DH + c0) = v;
            }
        }
    }
}

// ---------------------------------------------------------------------------
__global__ void __launch_bounds__(256) proj_kv_kernel(
    const float* __restrict__ mems, const float* __restrict__ rc,
    const float* __restrict__ utt, const float* __restrict__ W,
    const float* __restrict__ bias)
{
    __shared__ ProjSmem s;
    const int t0 = blockIdx.x * 128;
    const int cb = blockIdx.y, b = blockIdx.z;
    PROJ_PROLOG;

    auto gather = [&](int t) -> const float* {
        if (t < MMEM)      return mems + ((size_t)t * BB + b) * DDIM;
        if (t < MMEM + RR) return rc   + ((size_t)(t - MMEM) * BB + b) * DDIM;
        if (t < KLL)       return utt  + ((size_t)(t - MMEM - RR) * BB + b) * DDIM;
        return nullptr;
    };
    const int ta = t0 + wid * 16 + g;
    const float* ar0 = gather(ta);
    const float* ar1 = gather(ta + 8);
    const float* wr0 = W + (size_t)(cb * 64 + (wid >> 1) * 16 + g) * DDIM;
    const float* wr1 = wr0 + 8 * DDIM;

    for (int k0 = 0; k0 < DDIM; k0 += 32)
        proj_chunk(s, ar0, ar1, k0, wr0, wr1, k0, lid, wid, acc);

    float* dst = (cb < HH) ? g_k : g_v;
    const int h = cb & 7;
    const size_t nb = ((size_t)(b * HH + h)) * KLL;
#pragma unroll
    for (int mt = 0; mt < 2; mt++)
#pragma unroll
    for (int nt = 0; nt < 4; nt++) {
        const int c0 = warpN + nt * 8 + 2 * tg;
        const float bx = bias[cb * 64 + c0], by = bias[cb * 64 + c0 + 1];
#pragma unroll
        for (int rh = 0; rh < 2; rh++) {
            const int t = t0 + warpM + mt * 16 + rh * 8 + g;
            if (t < KLL) {
                float2 v;
                v.x = acc[mt][nt][rh * 2 + 0] + bx;
                v.y = acc[mt][nt][rh * 2 + 1] + by;
                *(float2*)(dst + (nb + t) * DH + c0) = v;
            }
        }
    }
}

// ---------------------------------------------------------------------------
// Flash attention on tensor cores. Block = (q-tile 64, head n). 8 warps:
// QK/PV warp tile 16(m) x 32(n): warpM=(wid&3)*16, nhalf=wid>>2.
// ---------------------------------------------------------------------------
#define FSM_K  4096
#define FSM_V  8192
#define FSM_P  12288
#define FSM_M  16384
#define FSM_L  16448
#define FSM_C  16512
#define FSM_PM 16576
#define FSM_PS 16704
#define FSM_TOT 16832   // floats

__global__ void __launch_bounds__(256) flash_kernel(const void* __restrict__ lengths)
{
    extern __shared__ float sm[];
    unsigned* Qf = (unsigned*)sm;
    unsigned* Kf = (unsigned*)(sm + FSM_K);
    unsigned* Vf = (unsigned*)(sm + FSM_V);
    unsigned* Pf = (unsigned*)(sm + FSM_P);
    float* sM = sm + FSM_M;
    float* sL = sm + FSM_L;
    float* sC = sm + FSM_C;
    float* pmax = sm + FSM_PM;   // [2][64]
    float* psum = sm + FSM_PS;   // [2][64]

    const int qt = gridDim.x - 1 - blockIdx.x;
    const int n = blockIdx.y, b = n >> 3;
    const int q0 = qt * 64;
    const int tid = threadIdx.x;
    const int lid = tid & 31, wid = tid >> 5;
    const int g = lid >> 2, tg = lid & 3;
    const int warpM = (wid & 3) * 16;
    const int nhalf = wid >> 2;
    const int warpN = nhalf * 32;

    int ml = read_len(lengths, 0);
#pragma unroll
    for (int i = 1; i < BB; i++) { int v = read_len(lengths, i); if (v > ml) ml = v; }
    const int klen = read_len(lengths, b) + MMEM + (TQL - ml - SSUM);

    if (tid < 64) { sM[tid] = NEG_INF; sL[tid] = 0.f; }

    // Q -> A-frag smem (units: m16 = wid>>1, k8 = (wid&1)*4 + u)
    {
        const int m16 = wid >> 1;
        const int qr = q0 + m16 * 16 + g;
        const float* r0 = (qr < TQL) ? g_q + ((size_t)n * TQL + qr) * DH : nullptr;
        const float* r1 = (qr + 8 < TQL) ? g_q + ((size_t)n * TQL + qr + 8) * DH : nullptr;
#pragma unroll
        for (int u = 0; u < 4; u++) {
            const int k8 = (wid & 1) * 4 + u;
            const int c = k8 * 8 + tg;
            uint4 w;
            w.x = f2t(r0 ? r0[c] : 0.f);
            w.y = f2t(r1 ? r1[c] : 0.f);
            w.z = f2t(r0 ? r0[c + 4] : 0.f);
            w.w = f2t(r1 ? r1[c + 4] : 0.f);
            ((uint4*)Qf)[(m16 * 8 + k8) * 32 + lid] = w;
        }
    }

    float o[4][4];
#pragma unroll
    for (int nt = 0; nt < 4; nt++)
#pragma unroll
        for (int i = 0; i < 4; i++) o[nt][i] = 0.f;

    const int nkt = min(17, qt + 2);
    for (int kt = 0; kt < nkt; kt++) {
        const int k0 = kt * 64;
        __syncthreads();   // Kf/Vf free (prev PV done); also covers Q/init first iter
        // K -> B-frag (n16 = kseq/16, k8 = d/8)
        {
            const int n16 = wid >> 1;
            const int kr = k0 + n16 * 16 + g;
            const float* r0 = g_k + ((size_t)n * KLL + (kr < KLL ? kr : 0)) * DH;
            const float* r1 = g_k + ((size_t)n * KLL + (kr + 8 < KLL ? kr + 8 : 0)) * DH;
#pragma unroll
            for (int u = 0; u < 4; u++) {
                const int k8 = (wid & 1) * 4 + u;
                const int c = k8 * 8 + tg;
                uint4 w;
                w.x = f2t(r0[c]); w.y = f2t(r0[c + 4]);
                w.z = f2t(r1[c]); w.w = f2t(r1[c + 4]);
                ((uint4*)Kf)[(n16 * 8 + k8) * 32 + lid] = w;
            }
        }
        // V -> B-frag (n16 = d/16, k8 = kseq/8)
        {
            const int n16 = wid >> 1;
            const int d0 = n16 * 16 + g;
#pragma unroll
            for (int u = 0; u < 4; u++) {
                const int k8 = (wid & 1) * 4 + u;
                const int kr = k0 + k8 * 8 + tg;
                const float* r0 = g_v + ((size_t)n * KLL + (kr < KLL ? kr : 0)) * DH;
                const float* r1 = g_v + ((size_t)n * KLL + (kr + 4 < KLL ? kr + 4 : 0)) * DH;
                uint4 w;
                w.x = f2t(r0[d0]); w.y = f2t(r1[d0]);
                w.z = f2t(r0[d0 + 8]); w.w = f2t(r1[d0 + 8]);
                ((uint4*)Vf)[(n16 * 8 + k8) * 32 + lid] = w;
            }
        }
        __syncthreads();

        // S = Q K^T
        float s[4][4];
#pragma unroll
        for (int nt = 0; nt < 4; nt++)
#pragma unroll
            for (int i = 0; i < 4; i++) s[nt][i] = 0.f;
        {
            const uint4* Q4 = (const uint4*)Qf;
            const uint4* K4 = (const uint4*)Kf;
            const int m16 = wid & 3, n16 = nhalf * 2;
#pragma unroll
            for (int k8 = 0; k8 < 8; k8++) {
                uint4 a  = Q4[(m16 * 8 + k8) * 32 + lid];
                uint4 b0 = K4[(n16 * 8 + k8) * 32 + lid];
                uint4 b1 = K4[((n16 + 1) * 8 + k8) * 32 + lid];
                mma_t(s[0], a, b0.x, b0.y); mma_t(s[1], a, b0.z, b0.w);
                mma_t(s[2], a, b1.x, b1.y); mma_t(s[3], a, b1.z, b1.w);
            }
        }

        // mask + partial row max
        const int qlo = q0 + warpM + g, qhi = qlo + 8;
        float mx0 = NEG_INF, mx1 = NEG_INF;
#pragma unroll
        for (int nt = 0; nt < 4; nt++) {
            const int kb = k0 + warpN + nt * 8 + 2 * tg;
            s[nt][0] = (kb     <= qlo + MMEM && kb     < klen) ? s[nt][0] : NEG_INF;
            s[nt][1] = (kb + 1 <= qlo + MMEM && kb + 1 < klen) ? s[nt][1] : NEG_INF;
            s[nt][2] = (kb     <= qhi + MMEM && kb     < klen) ? s[nt][2] : NEG_INF;
            s[nt][3] = (kb + 1 <= qhi + MMEM && kb + 1 < klen) ? s[nt][3] : NEG_INF;
            mx0 = fmaxf(mx0, fmaxf(s[nt][0], s[nt][1]));
            mx1 = fmaxf(mx1, fmaxf(s[nt][2], s[nt][3]));
        }
        mx0 = fmaxf(mx0, __shfl_xor_sync(0xffffffffu, mx0, 1));
        mx0 = fmaxf(mx0, __shfl_xor_sync(0xffffffffu, mx0, 2));
        mx1 = fmaxf(mx1, __shfl_xor_sync(0xffffffffu, mx1, 1));
        mx1 = fmaxf(mx1, __shfl_xor_sync(0xffffffffu, mx1, 2));
        if (tg == 0) {
            pmax[nhalf * 64 + warpM + g] = mx0;
            pmax[nhalf * 64 + warpM + 8 + g] = mx1;
        }
        __syncthreads();
        if (tid < 64) {
            const float mo = sM[tid];
            const float mn = fmaxf(mo, fmaxf(pmax[tid], pmax[64 + tid]));
            sM[tid] = mn;
            sC[tid] = __expf(mo - mn);
        }
        __syncthreads();

        // exp, P-frag store, O rescale, partial row sum
        const float mlo = sM[warpM + g], mhi = sM[warpM + 8 + g];
        const float clo = sC[warpM + g], chi = sC[warpM + 8 + g];
        float sum0 = 0.f, sum1 = 0.f;
        const int m16 = wid & 3;
#pragma unroll
        for (int nt = 0; nt < 4; nt++) {
            const float p0 = __expf(s[nt][0] - mlo);
            const float p1 = __expf(s[nt][1] - mlo);
            const float p2 = __expf(s[nt][2] - mhi);
            const float p3 = __expf(s[nt][3] - mhi);
            sum0 += p0 + p1; sum1 += p2 + p3;
            const unsigned base = (unsigned)((m16 * 8 + nhalf * 4 + nt) * 128);
            const int ln0 = g * 4 + ((2 * tg) & 3);
            const int ln1 = g * 4 + ((2 * tg + 1) & 3);
            const int sl = 2 * (tg >> 1);
            Pf[base + ln0 * 4 + sl + 0] = f2t(p0);
            Pf[base + ln1 * 4 + sl + 0] = f2t(p1);
            Pf[base + ln0 * 4 + sl + 1] = f2t(p2);
            Pf[base + ln1 * 4 + sl + 1] = f2t(p3);
            o[nt][0] *= clo; o[nt][1] *= clo;
            o[nt][2] *= chi; o[nt][3] *= chi;
        }
        sum0 += __shfl_xor_sync(0xffffffffu, sum0, 1);
        sum0 += __shfl_xor_sync(0xffffffffu, sum0, 2);
        sum1 += __shfl_xor_sync(0xffffffffu, sum1, 1);
        sum1 += __shfl_xor_sync(0xffffffffu, sum1, 2);
        if (tg == 0) {
            psum[nhalf * 64 + warpM + g] = sum0;
            psum[nhalf * 64 + warpM + 8 + g] = sum1;
        }
        __syncthreads();
        if (tid < 64)
            sL[tid] = sL[tid] * sC[tid] + psum[tid] + psum[64 + tid];

        // O += P V
        {
            const uint4* P4 = (const uint4*)Pf;
            const uint4* V4 = (const uint4*)Vf;
            const int n16 = nhalf * 2;
#pragma unroll
            for (int k8 = 0; k8 < 8; k8++) {
                uint4 a  = P4[(m16 * 8 + k8) * 32 + lid];
                uint4 b0 = V4[(n16 * 8 + k8) * 32 + lid];
                uint4 b1 = V4[((n16 + 1) * 8 + k8) * 32 + lid];
                mma_t(o[0], a, b0.x, b0.y); mma_t(o[1], a, b0.z, b0.w);
                mma_t(o[2], a, b1.x, b1.y); mma_t(o[3], a, b1.z, b1.w);
            }
        }
    }

    __syncthreads();
    const int qlo = q0 + warpM + g, qhi = qlo + 8;
    const float llo = 1.f / sL[warpM + g], lhi = 1.f / sL[warpM + 8 + g];
#pragma unroll
    for (int nt = 0; nt < 4; nt++) {
        const int c = warpN + nt * 8 + 2 * tg;
        if (qlo < TQL) {
            float2 v; v.x = o[nt][0] * llo; v.y = o[nt][1] * llo;
            *(float2*)(g_attn + ((size_t)n * TQL + qlo) * DH + c) = v;
        }
        if (qhi < TQL) {
            float2 v; v.x = o[nt][2] * lhi; v.y = o[nt][3] * lhi;
            *(float2*)(g_attn + ((size_t)n * TQL + qhi) * DH + c) = v;
        }
    }
}

// ---------------------------------------------------------------------------
__global__ void __launch_bounds__(256) out_proj_kernel(
    const float* __restrict__ W, const float* __restrict__ bias,
    float* __restrict__ out)
{
    __shared__ ProjSmem s;
    const int t0 = blockIdx.x * 128;
    const int cby = blockIdx.y, b = blockIdx.z;
    PROJ_PROLOG;

    const int ta = t0 + wid * 16 + g;
    const float* wr0 = W + (size_t)(cby * 64 + (wid >> 1) * 16 + g) * DDIM;
    const float* wr1 = wr0 + 8 * DDIM;

    for (int k0 = 0; k0 < DDIM; k0 += 32) {
        const int hh = k0 >> 6, ko = k0 & 63;
        const float* ar0 = (ta < TQL) ?
            g_attn + ((size_t)(b * HH + hh) * TQL + ta) * DH + ko : nullptr;
        const float* ar1 = (ta + 8 < TQL) ?
            g_attn + ((size_t)(b * HH + hh) * TQL + ta + 8) * DH + ko : nullptr;
        proj_chunk(s, ar0, ar1, 0, wr0, wr1, k0, lid, wid, acc);
    }

    const size_t mems_base = (size_t)(TQL - SSUM) * BB * DDIM;
#pragma unroll
    for (int mt = 0; mt < 2; mt++)
#pragma unroll
    for (int nt = 0; nt < 4; nt++) {
        const int c0 = cby * 64 + warpN + nt * 8 + 2 * tg;
        const float bx = bias[c0], by = bias[c0 + 1];
#pragma unroll
        for (int rh = 0; rh < 2; rh++) {
            const int tt = t0 + warpM + mt * 16 + rh * 8 + g;
            if (tt >= TQL - 1) continue;   // drop t=1071 and padding
            float2 v;
            v.x = acc[mt][nt][rh * 2 + 0] + bx;
            v.y = acc[mt][nt][rh * 2 + 1] + by;
            if (tt < TQL - SSUM) {
                *(float2*)(out + ((size_t)tt * BB + b) * DDIM + c0) = v;
            } else {
                v.x = fminf(fmaxf(v.x, -10.f), 10.f);
                v.y = fminf(fmaxf(v.y, -10.f), 10.f);
                *(float2*)(out + mems_base +
                           ((size_t)(tt - (TQL - SSUM)) * BB + b) * DDIM + c0) = v;
            }
        }
    }
}

// ---------------------------------------------------------------------------
extern "C" void kernel_launch(void* const* d_in, const int* in_sizes, int n_in,
                              void* d_out, int out_size)
{
    const float* utt  = (const float*)d_in[0];
    const void*  len  = (const void*)d_in[1];
    const float* rc   = (const float*)d_in[2];
    const float* summ = (const float*)d_in[3];
    const float* mems = (const float*)d_in[4];
    // d_in[5] = attention_mask (deterministic; computed analytically in-kernel)
    const float* Wq   = (const float*)d_in[6];
    const float* bq   = (const float*)d_in[7];
    const float* Wkv  = (const float*)d_in[8];
    const float* bkv  = (const float*)d_in[9];
    const float* Wo   = (const float*)d_in[10];
    const float* bo   = (const float*)d_in[11];
    float* out = (float*)d_out;

    const int flash_smem = FSM_TOT * (int)sizeof(float);   // 67328 B
    cudaFuncSetAttribute(flash_kernel,
                         cudaFuncAttributeMaxDynamicSharedMemorySize, flash_smem);

    proj_q_kernel  <<<dim3(9, 8, BB), 256>>>(utt, rc, summ, Wq, bq);
    proj_kv_kernel <<<dim3(9, 16, BB), 256>>>(mems, rc, utt, Wkv, bkv);
    flash_kernel   <<<dim3(17, NH), 256, flash_smem>>>(len);
    out_proj_kernel<<<dim3(9, 8, BB), 256>>>(Wo, bo, out);
}

// round 5
// speedup vs baseline: 3.1870x; 1.6046x over previous
#include <cuda_runtime.h>
#include <cstdint>

// Emformer layer, sm_103a. Round 5: coalesced LDG + fragment-order smem staging
// (8x L1tex wavefront reduction), V transposed for flash, polynomial exp.
// T=1024 B=16 D=512 H=8 R=32 S=16 M=16  TQ=KL=1072, d_head=64, B*H=128.

#define TT    1024
#define BB    16
#define DDIM  512
#define HH    8
#define RR    32
#define SSUM  16
#define MMEM  16
#define TQL   1072
#define KLL   1072
#define DH    64
#define NH    128
#define NEG_INF (-100000000.0f)
#define QSCALE  (0.125f)

__device__ float g_q   [(size_t)NH * TQL * DH + 2048];
__device__ float g_k   [(size_t)NH * KLL * DH + 2048];
__device__ float g_vT  [(size_t)NH * DH * KLL + 2048];   // [n][d][kseq]
__device__ float g_attn[(size_t)NH * TQL * DH + 2048];

// lengths may be int32 (JAX default) or int64; values in [512,1024] nonzero.
__device__ __forceinline__ int read_len(const void* lptr, int b) {
    const int* p32 = (const int*)lptr;
    const bool is64 = (p32[1] == 0) & (p32[3] == 0) & (p32[5] == 0);
    return is64 ? (int)(((const long long*)lptr)[b]) : p32[b];
}

__device__ __forceinline__ unsigned f2t(float x) {
    unsigned r;
    asm("cvt.rna.tf32.f32 %0, %1;" : "=r"(r) : "f"(x));
    return r;
}
__device__ __forceinline__ void mma_t(float c[4], uint4 a, unsigned b0, unsigned b1) {
    asm("mma.sync.aligned.m16n8k8.row.col.f32.tf32.tf32.f32 "
        "{%0,%1,%2,%3},{%4,%5,%6,%7},{%8,%9},{%0,%1,%2,%3};"
        : "+f"(c[0]), "+f"(c[1]), "+f"(c[2]), "+f"(c[3])
        : "r"(a.x), "r"(a.y), "r"(a.z), "r"(a.w), "r"(b0), "r"(b1));
}

// fast exp on the FMA pipe (x <= 0; masked values ~ -1e8 -> 0)
__device__ __forceinline__ float fexp(float x) {
    float t = x * 1.44269504089f;
    t = fmaxf(t, -125.0f);
    int ii = __float2int_rn(t);
    float f = t - (float)ii;
    float p = fmaf(f, 0.00961812910f, 0.05550410866f);
    p = fmaf(f, p, 0.24022650696f);
    p = fmaf(f, p, 0.69314718056f);
    p = fmaf(f, p, 1.0f);
    return __int_as_float((ii + 127) << 23) * p;
}

// Fragment-order smem. Unit (16 rows x 8 k) = 128 words, padded stride 132
// words (33 uint4). Word (r,c): lane=(r&7)*4+(c&3);
// A slot = ((r&15)>>3) + 2*((c&7)>>2);  B slot = 2*((r&15)>>3) + ((c&7)>>2).
#define UPW 132
#define UP4 33

__device__ __forceinline__ void sts_afrag(unsigned* S, int k8n, int r, int c0, float4 v) {
    const int unit = (r >> 4) * k8n + (c0 >> 3);
    const int base = unit * UPW + (r & 7) * 16 + ((r & 15) >> 3) + 2 * ((c0 & 7) >> 2);
    S[base] = f2t(v.x); S[base + 4] = f2t(v.y);
    S[base + 8] = f2t(v.z); S[base + 12] = f2t(v.w);
}
__device__ __forceinline__ void sts_bfrag(unsigned* S, int k8n, int r, int c0, float4 v) {
    const int unit = (r >> 4) * k8n + (c0 >> 3);
    const int base = unit * UPW + (r & 7) * 16 + 2 * ((r & 15) >> 3) + ((c0 & 7) >> 2);
    S[base] = f2t(v.x); S[base + 4] = f2t(v.y);
    S[base + 8] = f2t(v.z); S[base + 12] = f2t(v.w);
}

// ---------------------------------------------------------------------------
// Projection core: block tile 128x64, K-chunk 32, 8 warps (4m x 2n), 32x32/warp.
// ---------------------------------------------------------------------------
struct ProjSmem { unsigned Af[32 * UPW]; unsigned Bf[16 * UPW]; };

__device__ __forceinline__ void proj_mma(const ProjSmem& s, int lid, int wid,
                                         float acc[2][4][4]) {
    const uint4* A4 = (const uint4*)s.Af;
    const uint4* B4 = (const uint4*)s.Bf;
    const int m16 = (wid & 3) * 2, n16 = (wid >> 2) * 2;
#pragma unroll
    for (int k8 = 0; k8 < 4; k8++) {
        uint4 a0 = A4[(m16 * 4 + k8) * UP4 + lid];
        uint4 a1 = A4[((m16 + 1) * 4 + k8) * UP4 + lid];
        uint4 b0 = B4[(n16 * 4 + k8) * UP4 + lid];
        uint4 b1 = B4[((n16 + 1) * 4 + k8) * UP4 + lid];
        mma_t(acc[0][0], a0, b0.x, b0.y); mma_t(acc[0][1], a0, b0.z, b0.w);
        mma_t(acc[0][2], a0, b1.x, b1.y); mma_t(acc[0][3], a0, b1.z, b1.w);
        mma_t(acc[1][0], a1, b0.x, b0.y); mma_t(acc[1][1], a1, b0.z, b0.w);
        mma_t(acc[1][2], a1, b1.x, b1.y); mma_t(acc[1][3], a1, b1.z, b1.w);
    }
}

#define PROJ_PROLOG \
    const int tid = threadIdx.x; \
    const int lid = tid & 31, wid = tid >> 5; \
    const int g = lid >> 2, tg = lid & 3; \
    const int warpM = (wid & 3) * 32, warpN = (wid >> 2) * 32; \
    const int lr = tid >> 3;           /* 0..31 loader row */ \
    const int lc = (tid & 7) * 4;      /* 0..28 loader col */ \
    float acc[2][4][4]; \
    _Pragma("unroll") for (int mt = 0; mt < 2; mt++) \
    _Pragma("unroll") for (int nt = 0; nt < 4; nt++) \
    _Pragma("unroll") for (int i = 0; i < 4; i++) acc[mt][nt][i] = 0.f;

#define Z4 make_float4(0.f, 0.f, 0.f, 0.f)

// ---------------------------------------------------------------------------
__global__ void __launch_bounds__(256) proj_q_kernel(
    const float* __restrict__ utt, const float* __restrict__ rc,
    const float* __restrict__ summ, const float* __restrict__ W,
    const float* __restrict__ bias)
{
    __shared__ ProjSmem s;
    const int t0 = blockIdx.x * 128;
    const int h = blockIdx.y, b = blockIdx.z;
    PROJ_PROLOG;

    auto gather = [&](int t) -> const float* {
        if (t < RR)      return rc   + ((size_t)t * BB + b) * DDIM;
        if (t < RR + TT) return utt  + ((size_t)(t - RR) * BB + b) * DDIM;
        if (t < TQL)     return summ + ((size_t)(t - RR - TT) * BB + b) * DDIM;
        return nullptr;
    };
    const float* ap[4];
#pragma unroll
    for (int i = 0; i < 4; i++) ap[i] = gather(t0 + i * 32 + lr);
    const float* bp0 = W + (size_t)(h * 64 + lr) * DDIM;
    const float* bp1 = W + (size_t)(h * 64 + 32 + lr) * DDIM;

    float4 pa[4], pb[2];
#pragma unroll
    for (int i = 0; i < 4; i++) pa[i] = ap[i] ? *(const float4*)(ap[i] + lc) : Z4;
    pb[0] = *(const float4*)(bp0 + lc); pb[1] = *(const float4*)(bp1 + lc);

    for (int k0 = 0; k0 < DDIM; k0 += 32) {
        __syncthreads();
#pragma unroll
        for (int i = 0; i < 4; i++) sts_afrag(s.Af, 4, i * 32 + lr, lc, pa[i]);
        sts_bfrag(s.Bf, 4, lr, lc, pb[0]);
        sts_bfrag(s.Bf, 4, 32 + lr, lc, pb[1]);
        __syncthreads();
        if (k0 + 32 < DDIM) {
            const int kn = k0 + 32 + lc;
#pragma unroll
            for (int i = 0; i < 4; i++) pa[i] = ap[i] ? *(const float4*)(ap[i] + kn) : Z4;
            pb[0] = *(const float4*)(bp0 + kn); pb[1] = *(const float4*)(bp1 + kn);
        }
        proj_mma(s, lid, wid, acc);
    }

    const size_t nb = ((size_t)(b * HH + h)) * TQL;
#pragma unroll
    for (int mt = 0; mt < 2; mt++)
#pragma unroll
    for (int nt = 0; nt < 4; nt++) {
        const int c0 = warpN + nt * 8 + 2 * tg;
        const float bx = bias[h * 64 + c0], by = bias[h * 64 + c0 + 1];
#pragma unroll
        for (int rh = 0; rh < 2; rh++) {
            const int t = t0 + warpM + mt * 16 + rh * 8 + g;
            if (t < TQL) {
                float2 v;
                v.x = (acc[mt][nt][rh * 2 + 0] + bx) * QSCALE;
                v.y = (acc[mt][nt][rh * 2 + 1] + by) * QSCALE;
                *(float2*)(g_q + (nb + t) * DH + c0) = v;
            }
        }
    }
}

// ---------------------------------------------------------------------------
__global__ void __launch_bounds__(256) proj_kv_kernel(
    const float* __restrict__ mems, const float* __restrict__ rc,
    const float* __restrict__ utt, const float* __restrict__ W,
    const float* __restrict__ bias)
{
    __shared__ ProjSmem s;
    const int t0 = blockIdx.x * 128;
    const int cb = blockIdx.y, b = blockIdx.z;
    PROJ_PROLOG;

    auto gather = [&](int t) -> const float* {
        if (t < MMEM)      return mems + ((size_t)t * BB + b) * DDIM;
        if (t < MMEM + RR) return rc   + ((size_t)(t - MMEM) * BB + b) * DDIM;
        if (t < KLL)       return utt  + ((size_t)(t - MMEM - RR) * BB + b) * DDIM;
        return nullptr;
    };
    const float* ap[4];
#pragma unroll
    for (int i = 0; i < 4; i++) ap[i] = gather(t0 + i * 32 + lr);
    const float* bp0 = W + (size_t)(cb * 64 + lr) * DDIM;
    const float* bp1 = W + (size_t)(cb * 64 + 32 + lr) * DDIM;

    float4 pa[4], pb[2];
#pragma unroll
    for (int i = 0; i < 4; i++) pa[i] = ap[i] ? *(const float4*)(ap[i] + lc) : Z4;
    pb[0] = *(const float4*)(bp0 + lc); pb[1] = *(const float4*)(bp1 + lc);

    for (int k0 = 0; k0 < DDIM; k0 += 32) {
        __syncthreads();
#pragma unroll
        for (int i = 0; i < 4; i++) sts_afrag(s.Af, 4, i * 32 + lr, lc, pa[i]);
        sts_bfrag(s.Bf, 4, lr, lc, pb[0]);
        sts_bfrag(s.Bf, 4, 32 + lr, lc, pb[1]);
        __syncthreads();
        if (k0 + 32 < DDIM) {
            const int kn = k0 + 32 + lc;
#pragma unroll
            for (int i = 0; i < 4; i++) pa[i] = ap[i] ? *(const float4*)(ap[i] + kn) : Z4;
            pb[0] = *(const float4*)(bp0 + kn); pb[1] = *(const float4*)(bp1 + kn);
        }
        proj_mma(s, lid, wid, acc);
    }

    const int h = cb & 7;
    const int n = b * HH + h;
#pragma unroll
    for (int mt = 0; mt < 2; mt++)
#pragma unroll
    for (int nt = 0; nt < 4; nt++) {
        const int c0 = warpN + nt * 8 + 2 * tg;
        const float bx = bias[cb * 64 + c0], by = bias[cb * 64 + c0 + 1];
#pragma unroll
        for (int rh = 0; rh < 2; rh++) {
            const int t = t0 + warpM + mt * 16 + rh * 8 + g;
            if (t < KLL) {
                const float vx = acc[mt][nt][rh * 2 + 0] + bx;
                const float vy = acc[mt][nt][rh * 2 + 1] + by;
                if (cb < HH) {
                    float2 v; v.x = vx; v.y = vy;
                    *(float2*)(g_k + (((size_t)n) * KLL + t) * DH + c0) = v;
                } else {
                    g_vT[((size_t)n * DH + c0) * KLL + t] = vx;
                    g_vT[((size_t)n * DH + c0 + 1) * KLL + t] = vy;
                }
            }
        }
    }
}

// ---------------------------------------------------------------------------
// Flash attention (tensor). Block = (q-tile 64, head n). 8 warps.
// ---------------------------------------------------------------------------
#define FQO 0
#define FKO (32 * UPW)
#define FVO (64 * UPW)
#define FPO (96 * UPW)
#define FMO (128 * UPW)              // floats from here
#define FLO (FMO + 64)
#define FCO (FMO + 128)
#define FPM (FMO + 192)
#define FPS (FMO + 320)
#define FTOT (FMO + 448)

__global__ void __launch_bounds__(256) flash_kernel(const void* __restrict__ lengths)
{
    extern __shared__ float sm[];
    unsigned* Qf = (unsigned*)sm + FQO;
    unsigned* Kf = (unsigned*)sm + FKO;
    unsigned* Vf = (unsigned*)sm + FVO;
    unsigned* Pf = (unsigned*)sm + FPO;
    float* sM = sm + FMO;
    float* sL = sm + FLO;
    float* sC = sm + FCO;
    float* pmax = sm + FPM;
    float* psum = sm + FPS;

    const int qt = gridDim.x - 1 - blockIdx.x;
    const int n = blockIdx.y, b = n >> 3;
    const int q0 = qt * 64;
    const int tid = threadIdx.x;
    const int lid = tid & 31, wid = tid >> 5;
    const int g = lid >> 2, tg = lid & 3;
    const int warpM = (wid & 3) * 16;
    const int nhalf = wid >> 2;
    const int warpN = nhalf * 32;
    const int ldr = tid >> 4;          // 0..15 loader row
    const int ldc = (tid & 15) * 4;    // 0..60 loader col

    int ml = read_len(lengths, 0);
#pragma unroll
    for (int i = 1; i < BB; i++) { int v = read_len(lengths, i); if (v > ml) ml = v; }
    const int klen = read_len(lengths, b) + MMEM + (TQL - ml - SSUM);

    if (tid < 64) { sM[tid] = NEG_INF; sL[tid] = 0.f; }

    // Q -> A-frag (64x64, k8n=8), coalesced
#pragma unroll
    for (int i = 0; i < 4; i++) {
        const int r = i * 16 + ldr;
        const int q = q0 + r;
        float4 v = (q < TQL) ? *(const float4*)(g_q + ((size_t)n * TQL + q) * DH + ldc) : Z4;
        sts_afrag(Qf, 8, r, ldc, v);
    }

    float o[4][4];
#pragma unroll
    for (int nt = 0; nt < 4; nt++)
#pragma unroll
        for (int i = 0; i < 4; i++) o[nt][i] = 0.f;

    const int nkt = min(17, qt + 2);
    for (int kt = 0; kt < nkt; kt++) {
        const int k0 = kt * 64;
        __syncthreads();
        // K -> B-frag (rows = kseq, cols = d), coalesced; OOB rows read padded mem (masked later)
#pragma unroll
        for (int i = 0; i < 4; i++) {
            const int r = i * 16 + ldr;
            float4 v = *(const float4*)(g_k + ((size_t)n * KLL + k0 + r) * DH + ldc);
            sts_bfrag(Kf, 8, r, ldc, v);
        }
        // V -> B-frag (rows = d, cols = kseq) from transposed g_vT, coalesced
#pragma unroll
        for (int i = 0; i < 4; i++) {
            const int d = i * 16 + ldr;
            float4 v = *(const float4*)(g_vT + ((size_t)n * DH + d) * KLL + k0 + ldc);
            sts_bfrag(Vf, 8, d, ldc, v);
        }
        __syncthreads();

        // S = Q K^T
        float s[4][4];
#pragma unroll
        for (int nt = 0; nt < 4; nt++)
#pragma unroll
            for (int i = 0; i < 4; i++) s[nt][i] = 0.f;
        {
            const uint4* Q4 = (const uint4*)Qf;
            const uint4* K4 = (const uint4*)Kf;
            const int m16 = wid & 3, n16 = nhalf * 2;
#pragma unroll
            for (int k8 = 0; k8 < 8; k8++) {
                uint4 a  = Q4[(m16 * 8 + k8) * UP4 + lid];
                uint4 b0 = K4[(n16 * 8 + k8) * UP4 + lid];
                uint4 b1 = K4[((n16 + 1) * 8 + k8) * UP4 + lid];
                mma_t(s[0], a, b0.x, b0.y); mma_t(s[1], a, b0.z, b0.w);
                mma_t(s[2], a, b1.x, b1.y); mma_t(s[3], a, b1.z, b1.w);
            }
        }

        // mask + partial row max
        const int qlo = q0 + warpM + g, qhi = qlo + 8;
        float mx0 = NEG_INF, mx1 = NEG_INF;
#pragma unroll
        for (int nt = 0; nt < 4; nt++) {
            const int kb = k0 + warpN + nt * 8 + 2 * tg;
            s[nt][0] = (kb     <= qlo + MMEM && kb     < klen) ? s[nt][0] : NEG_INF;
            s[nt][1] = (kb + 1 <= qlo + MMEM && kb + 1 < klen) ? s[nt][1] : NEG_INF;
            s[nt][2] = (kb     <= qhi + MMEM && kb     < klen) ? s[nt][2] : NEG_INF;
            s[nt][3] = (kb + 1 <= qhi + MMEM && kb + 1 < klen) ? s[nt][3] : NEG_INF;
            mx0 = fmaxf(mx0, fmaxf(s[nt][0], s[nt][1]));
            mx1 = fmaxf(mx1, fmaxf(s[nt][2], s[nt][3]));
        }
        mx0 = fmaxf(mx0, __shfl_xor_sync(0xffffffffu, mx0, 1));
        mx0 = fmaxf(mx0, __shfl_xor_sync(0xffffffffu, mx0, 2));
        mx1 = fmaxf(mx1, __shfl_xor_sync(0xffffffffu, mx1, 1));
        mx1 = fmaxf(mx1, __shfl_xor_sync(0xffffffffu, mx1, 2));
        if (tg == 0) {
            pmax[nhalf * 64 + warpM + g] = mx0;
            pmax[nhalf * 64 + warpM + 8 + g] = mx1;
        }
        __syncthreads();
        if (tid < 64) {
            const float mo = sM[tid];
            const float mn = fmaxf(mo, fmaxf(pmax[tid], pmax[64 + tid]));
            sM[tid] = mn;
            sC[tid] = fexp(mo - mn);
        }
        __syncthreads();

        // exp (FMA-pipe poly), P-frag store, O rescale, partial row sum
        const float mlo = sM[warpM + g], mhi = sM[warpM + 8 + g];
        const float clo = sC[warpM + g], chi = sC[warpM + 8 + g];
        float sum0 = 0.f, sum1 = 0.f;
        const int m16 = wid & 3;
#pragma unroll
        for (int nt = 0; nt < 4; nt++) {
            const float p0 = fexp(s[nt][0] - mlo);
            const float p1 = fexp(s[nt][1] - mlo);
            const float p2 = fexp(s[nt][2] - mhi);
            const float p3 = fexp(s[nt][3] - mhi);
            sum0 += p0 + p1; sum1 += p2 + p3;
            const unsigned base = (unsigned)((m16 * 8 + nhalf * 4 + nt) * UPW);
            const int ln0 = g * 4 + ((2 * tg) & 3);
            const int ln1 = g * 4 + ((2 * tg + 1) & 3);
            const int sl = 2 * (tg >> 1);
            Pf[base + ln0 * 4 + sl + 0] = f2t(p0);
            Pf[base + ln1 * 4 + sl + 0] = f2t(p1);
            Pf[base + ln0 * 4 + sl + 1] = f2t(p2);
            Pf[base + ln1 * 4 + sl + 1] = f2t(p3);
            o[nt][0] *= clo; o[nt][1] *= clo;
            o[nt][2] *= chi; o[nt][3] *= chi;
        }
        sum0 += __shfl_xor_sync(0xffffffffu, sum0, 1);
        sum0 += __shfl_xor_sync(0xffffffffu, sum0, 2);
        sum1 += __shfl_xor_sync(0xffffffffu, sum1, 1);
        sum1 += __shfl_xor_sync(0xffffffffu, sum1, 2);
        if (tg == 0) {
            psum[nhalf * 64 + warpM + g] = sum0;
            psum[nhalf * 64 + warpM + 8 + g] = sum1;
        }
        __syncthreads();
        if (tid < 64)
            sL[tid] = sL[tid] * sC[tid] + psum[tid] + psum[64 + tid];

        // O += P V
        {
            const uint4* P4 = (const uint4*)Pf;
            const uint4* V4 = (const uint4*)Vf;
            const int n16 = nhalf * 2;
#pragma unroll
            for (int k8 = 0; k8 < 8; k8++) {
                uint4 a  = P4[(m16 * 8 + k8) * UP4 + lid];
                uint4 b0 = V4[(n16 * 8 + k8) * UP4 + lid];
                uint4 b1 = V4[((n16 + 1) * 8 + k8) * UP4 + lid];
                mma_t(o[0], a, b0.x, b0.y); mma_t(o[1], a, b0.z, b0.w);
                mma_t(o[2], a, b1.x, b1.y); mma_t(o[3], a, b1.z, b1.w);
            }
        }
    }

    __syncthreads();
    const int qlo = q0 + warpM + g, qhi = qlo + 8;
    const float llo = 1.f / sL[warpM + g], lhi = 1.f / sL[warpM + 8 + g];
#pragma unroll
    for (int nt = 0; nt < 4; nt++) {
        const int c = warpN + nt * 8 + 2 * tg;
        if (qlo < TQL) {
            float2 v; v.x = o[nt][0] * llo; v.y = o[nt][1] * llo;
            *(float2*)(g_attn + ((size_t)n * TQL + qlo) * DH + c) = v;
        }
        if (qhi < TQL) {
            float2 v; v.x = o[nt][2] * lhi; v.y = o[nt][3] * lhi;
            *(float2*)(g_attn + ((size_t)n * TQL + qhi) * DH + c) = v;
        }
    }
}

// ---------------------------------------------------------------------------
__global__ void __launch_bounds__(256) out_proj_kernel(
    const float* __restrict__ W, const float* __restrict__ bias,
    float* __restrict__ out)
{
    __shared__ ProjSmem s;
    const int t0 = blockIdx.x * 128;
    const int cby = blockIdx.y, b = blockIdx.z;
    PROJ_PROLOG;

    int tr[4]; bool tv[4];
#pragma unroll
    for (int i = 0; i < 4; i++) { tr[i] = t0 + i * 32 + lr; tv[i] = tr[i] < TQL; }
    const float* bp0 = W + (size_t)(cby * 64 + lr) * DDIM;
    const float* bp1 = W + (size_t)(cby * 64 + 32 + lr) * DDIM;

    auto lda = [&](int k0, float4* pa) {
        const int hh = k0 >> 6, ko = (k0 & 63) + lc;
#pragma unroll
        for (int i = 0; i < 4; i++)
            pa[i] = tv[i] ? *(const float4*)(g_attn +
                     ((size_t)(b * HH + hh) * TQL + tr[i]) * DH + ko) : Z4;
    };

    float4 pa[4], pb[2];
    lda(0, pa);
    pb[0] = *(const float4*)(bp0 + lc); pb[1] = *(const float4*)(bp1 + lc);

    for (int k0 = 0; k0 < DDIM; k0 += 32) {
        __syncthreads();
#pragma unroll
        for (int i = 0; i < 4; i++) sts_afrag(s.Af, 4, i * 32 + lr, lc, pa[i]);
        sts_bfrag(s.Bf, 4, lr, lc, pb[0]);
        sts_bfrag(s.Bf, 4, 32 + lr, lc, pb[1]);
        __syncthreads();
        if (k0 + 32 < DDIM) {
            lda(k0 + 32, pa);
            const int kn = k0 + 32 + lc;
            pb[0] = *(const float4*)(bp0 + kn); pb[1] = *(const float4*)(bp1 + kn);
        }
        proj_mma(s, lid, wid, acc);
    }

    const size_t mems_base = (size_t)(TQL - SSUM) * BB * DDIM;
#pragma unroll
    for (int mt = 0; mt < 2; mt++)
#pragma unroll
    for (int nt = 0; nt < 4; nt++) {
        const int c0 = cby * 64 + warpN + nt * 8 + 2 * tg;
        const float bx = bias[c0], by = bias[c0 + 1];
#pragma unroll
        for (int rh = 0; rh < 2; rh++) {
            const int tt = t0 + warpM + mt * 16 + rh * 8 + g;
            if (tt >= TQL - 1) continue;   // drop t=1071 and padding
            float2 v;
            v.x = acc[mt][nt][rh * 2 + 0] + bx;
            v.y = acc[mt][nt][rh * 2 + 1] + by;
            if (tt < TQL - SSUM) {
                *(float2*)(out + ((size_t)tt * BB + b) * DDIM + c0) = v;
            } else {
                v.x = fminf(fmaxf(v.x, -10.f), 10.f);
                v.y = fminf(fmaxf(v.y, -10.f), 10.f);
                *(float2*)(out + mems_base +
                           ((size_t)(tt - (TQL - SSUM)) * BB + b) * DDIM + c0) = v;
            }
        }
    }
}

// ---------------------------------------------------------------------------
extern "C" void kernel_launch(void* const* d_in, const int* in_sizes, int n_in,
                              void* d_out, int out_size)
{
    const float* utt  = (const float*)d_in[0];
    const void*  len  = (const void*)d_in[1];
    const float* rc   = (const float*)d_in[2];
    const float* summ = (const float*)d_in[3];
    const float* mems = (const float*)d_in[4];
    // d_in[5] = attention_mask (deterministic; computed analytically in-kernel)
    const float* Wq   = (const float*)d_in[6];
    const float* bq   = (const float*)d_in[7];
    const float* Wkv  = (const float*)d_in[8];
    const float* bkv  = (const float*)d_in[9];
    const float* Wo   = (const float*)d_in[10];
    const float* bo   = (const float*)d_in[11];
    float* out = (float*)d_out;

    const int flash_smem = FTOT * (int)sizeof(float);   // 69376 B
    cudaFuncSetAttribute(flash_kernel,
                         cudaFuncAttributeMaxDynamicSharedMemorySize, flash_smem);

    proj_q_kernel  <<<dim3(9, 8, BB), 256>>>(utt, rc, summ, Wq, bq);
    proj_kv_kernel <<<dim3(9, 16, BB), 256>>>(mems, rc, utt, Wkv, bkv);
    flash_kernel   <<<dim3(17, NH), 256, flash_smem>>>(len);
    out_proj_kernel<<<dim3(9, 8, BB), 256>>>(Wo, bo, out);
}